// round 4
// baseline (speedup 1.0000x reference)
#include <cuda_runtime.h>
#include <cstdint>

// Haar DWT2 on x:[8,64,512,512] f32 -> 4 subbands [8,64,256,256] packed
// subband-major into d_out (LL, LH, HL, HH).
//
// Round 3: persistent grid-stride with cross-iteration load prefetch.
// Work item = one (plane, out-row, col-pair): reads 2x float4 (rows 2i, 2i+1),
// writes 1x float2 to each of 4 subbands. Each thread runs ITER=8 items;
// next item's loads are issued before current item's stores so read traffic
// stays in flight while writes drain.

static constexpr int W_IN  = 512;
static constexpr int H_OUT = 256;
static constexpr int W_OUT = 256;
static constexpr long long PLANE_IN  = (long long)W_IN * W_IN;    // 262144
static constexpr long long PLANE_OUT = (long long)H_OUT * W_OUT;  // 65536
static constexpr long long SUBBAND_STRIDE = 512LL * PLANE_OUT;    // 33,554,432

static constexpr unsigned TOTAL_ITEMS = 512u * 256u * 128u;       // 16,777,216
static constexpr int ITER = 8;
static constexpr unsigned NTHREADS = TOTAL_ITEMS / ITER;          // 2,097,152
static constexpr unsigned BLOCK = 256;
static constexpr unsigned GRID = NTHREADS / BLOCK;                // 8192

__device__ __forceinline__ void item_addrs(const float* __restrict__ x, unsigned idx,
                                           const float4*& a0, const float4*& a1)
{
    const unsigned j2 = idx & 127u;          // col-pair 0..127
    const unsigned i  = (idx >> 7) & 255u;   // out-row
    const unsigned p  = idx >> 15;           // plane
    const float* base = x + (long long)p * PLANE_IN + (long long)(2u * i) * W_IN;
    a0 = (const float4*)base + j2;
    a1 = a0 + (W_IN / 4);
}

__global__ void __launch_bounds__(BLOCK)
haar_dwt2_kernel(const float* __restrict__ x, float* __restrict__ out)
{
    unsigned idx = blockIdx.x * BLOCK + threadIdx.x;
    const unsigned stride = GRID * BLOCK;    // 2^21 (compile-time)

    const float4 *a0, *a1;
    item_addrs(x, idx, a0, a1);
    float4 r0 = __ldg(a0);
    float4 r1 = __ldg(a1);

#pragma unroll
    for (int k = 0; k < ITER; ++k) {
        // Prefetch next item's loads before this item's stores.
        float4 n0, n1;
        const unsigned nidx = idx + stride;
        if (k < ITER - 1) {
            const float4 *b0, *b1;
            item_addrs(x, nidx, b0, b1);
            n0 = __ldg(b0);
            n1 = __ldg(b1);
        }

        // Haar on current item: pairs (r0.x,r0.y | r1.x,r1.y) and (r0.z,r0.w | r1.z,r1.w)
        float2 ll, lh, hl, hh;
        {
            const float apb = r0.x + r0.y, amb = r0.x - r0.y;
            const float cpd = r1.x + r1.y, cmd = r1.x - r1.y;
            ll.x = (apb + cpd) * 0.5f;
            lh.x = (apb - cpd) * 0.5f;
            hl.x = (amb + cmd) * 0.5f;
            hh.x = (amb - cmd) * 0.5f;
        }
        {
            const float apb = r0.z + r0.w, amb = r0.z - r0.w;
            const float cpd = r1.z + r1.w, cmd = r1.z - r1.w;
            ll.y = (apb + cpd) * 0.5f;
            lh.y = (apb - cpd) * 0.5f;
            hl.y = (amb + cmd) * 0.5f;
            hh.y = (amb - cmd) * 0.5f;
        }

        const unsigned j2 = idx & 127u;
        const unsigned i  = (idx >> 7) & 255u;
        const unsigned p  = idx >> 15;
        const long long obase = (long long)p * PLANE_OUT + (long long)i * W_OUT + 2u * j2;
        *(float2*)(out + obase)                      = ll;
        *(float2*)(out + obase +     SUBBAND_STRIDE) = lh;
        *(float2*)(out + obase + 2 * SUBBAND_STRIDE) = hl;
        *(float2*)(out + obase + 3 * SUBBAND_STRIDE) = hh;

        idx = nidx;
        r0 = n0;
        r1 = n1;
    }
}

extern "C" void kernel_launch(void* const* d_in, const int* in_sizes, int n_in,
                              void* d_out, int out_size)
{
    const float* x = (const float*)d_in[0];
    float* out = (float*)d_out;
    haar_dwt2_kernel<<<GRID, BLOCK>>>(x, out);
}

// round 7
// speedup vs baseline: 1.0133x; 1.0133x over previous
#include <cuda_runtime.h>
#include <cstdint>

// Haar DWT2 on x:[8,64,512,512] f32 -> 4 subbands [8,64,256,256] packed
// subband-major into d_out (LL, LH, HL, HH).
//
// Round 6 (= Round 4 resubmit; prior round was an infra failure, no data):
// R1 structure (best measured: 156.2us, DRAM 85.9%), single change:
// block 256 -> 512 (halves CTA count, doubles per-CTA contiguous address
// footprint). Kernel is at the HBM mixed read/write ceiling (~6.8 TB/s);
// all SM-side reshaping proved neutral in R2/R3.
//
// Each thread: 2 output columns of one output row.
//   reads  float4 from input rows 2i and 2i+1  (32 B)
//   writes float2 to each of 4 subbands        (32 B)

static constexpr int W_IN = 512;
static constexpr int H_OUT = 256;
static constexpr int W_OUT = 256;
static constexpr int PAIRS_PER_ROW = W_OUT / 2;                  // 128 threads per output row
static constexpr long long PLANE_IN  = (long long)W_IN * W_IN;   // 262144
static constexpr long long PLANE_OUT = (long long)H_OUT * W_OUT; // 65536
static constexpr long long SUBBAND_STRIDE = 512LL * PLANE_OUT;   // 33,554,432

static constexpr unsigned BLOCK = 512;

__global__ void __launch_bounds__(BLOCK)
haar_dwt2_kernel(const float* __restrict__ x, float* __restrict__ out)
{
    const unsigned tid = blockIdx.x * BLOCK + threadIdx.x;
    // tid layout: [plane p : 512][out-row i : 256][col-pair j2 : 128]
    const unsigned j2 = tid & (PAIRS_PER_ROW - 1);       // 0..127
    const unsigned i  = (tid >> 7) & (H_OUT - 1);        // 0..255
    const unsigned p  = tid >> 15;                       // 0..511

    const float* base = x + (long long)p * PLANE_IN + (long long)(2u * i) * W_IN;
    const float4 r0 = __ldg((const float4*)base + j2);              // row 2i
    const float4 r1 = __ldg((const float4*)base + (W_IN / 4) + j2); // row 2i+1

    const float s = 0.5f;

    float2 ll, lh, hl, hh;
    {
        const float apb = r0.x + r0.y, amb = r0.x - r0.y;
        const float cpd = r1.x + r1.y, cmd = r1.x - r1.y;
        ll.x = (apb + cpd) * s;
        lh.x = (apb - cpd) * s;
        hl.x = (amb + cmd) * s;
        hh.x = (amb - cmd) * s;
    }
    {
        const float apb = r0.z + r0.w, amb = r0.z - r0.w;
        const float cpd = r1.z + r1.w, cmd = r1.z - r1.w;
        ll.y = (apb + cpd) * s;
        lh.y = (apb - cpd) * s;
        hl.y = (amb + cmd) * s;
        hh.y = (amb - cmd) * s;
    }

    const long long obase = (long long)p * PLANE_OUT + (long long)i * W_OUT + 2u * j2;
    *(float2*)(out + obase)                      = ll;
    *(float2*)(out + obase +     SUBBAND_STRIDE) = lh;
    *(float2*)(out + obase + 2 * SUBBAND_STRIDE) = hl;
    *(float2*)(out + obase + 3 * SUBBAND_STRIDE) = hh;
}

extern "C" void kernel_launch(void* const* d_in, const int* in_sizes, int n_in,
                              void* d_out, int out_size)
{
    const float* x = (const float*)d_in[0];
    float* out = (float*)d_out;

    // total threads = 512 planes * 256 rows * 128 pairs = 16,777,216
    const unsigned total = 512u * 256u * 128u;
    const unsigned grid = total / BLOCK; // 32768
    haar_dwt2_kernel<<<grid, BLOCK>>>(x, out);
}

// round 8
// speedup vs baseline: 1.0268x; 1.0133x over previous
#include <cuda_runtime.h>
#include <cstdint>

// Haar DWT2 on x:[8,64,512,512] f32 -> 4 subbands [8,64,256,256] packed
// subband-major into d_out (LL, LH, HL, HH).
//
// Round 7: final knob on the CTA-granularity axis: BLOCK 512 -> 1024
// (16384 CTAs, 128 KiB contiguous read footprint per CTA). All measured
// variants (R1/R2/R3/R4) sit at 156-158us, 83-86% DRAM, ~6.7-6.8 TB/s:
// the kernel is at the HBM3e mixed 1:1 read/write stream ceiling. If this
// lands neutral too, the kernel is converged at the roofline.
//
// Each thread: 2 output columns of one output row.
//   reads  float4 from input rows 2i and 2i+1  (32 B)
//   writes float2 to each of 4 subbands        (32 B)

static constexpr int W_IN = 512;
static constexpr int H_OUT = 256;
static constexpr int W_OUT = 256;
static constexpr int PAIRS_PER_ROW = W_OUT / 2;                  // 128 threads per output row
static constexpr long long PLANE_IN  = (long long)W_IN * W_IN;   // 262144
static constexpr long long PLANE_OUT = (long long)H_OUT * W_OUT; // 65536
static constexpr long long SUBBAND_STRIDE = 512LL * PLANE_OUT;   // 33,554,432

static constexpr unsigned BLOCK = 1024;

__global__ void __launch_bounds__(BLOCK)
haar_dwt2_kernel(const float* __restrict__ x, float* __restrict__ out)
{
    const unsigned tid = blockIdx.x * BLOCK + threadIdx.x;
    // tid layout: [plane p : 512][out-row i : 256][col-pair j2 : 128]
    const unsigned j2 = tid & (PAIRS_PER_ROW - 1);       // 0..127
    const unsigned i  = (tid >> 7) & (H_OUT - 1);        // 0..255
    const unsigned p  = tid >> 15;                       // 0..511

    const float* base = x + (long long)p * PLANE_IN + (long long)(2u * i) * W_IN;
    const float4 r0 = __ldg((const float4*)base + j2);              // row 2i
    const float4 r1 = __ldg((const float4*)base + (W_IN / 4) + j2); // row 2i+1

    const float s = 0.5f;

    float2 ll, lh, hl, hh;
    {
        const float apb = r0.x + r0.y, amb = r0.x - r0.y;
        const float cpd = r1.x + r1.y, cmd = r1.x - r1.y;
        ll.x = (apb + cpd) * s;
        lh.x = (apb - cpd) * s;
        hl.x = (amb + cmd) * s;
        hh.x = (amb - cmd) * s;
    }
    {
        const float apb = r0.z + r0.w, amb = r0.z - r0.w;
        const float cpd = r1.z + r1.w, cmd = r1.z - r1.w;
        ll.y = (apb + cpd) * s;
        lh.y = (apb - cpd) * s;
        hl.y = (amb + cmd) * s;
        hh.y = (amb - cmd) * s;
    }

    const long long obase = (long long)p * PLANE_OUT + (long long)i * W_OUT + 2u * j2;
    *(float2*)(out + obase)                      = ll;
    *(float2*)(out + obase +     SUBBAND_STRIDE) = lh;
    *(float2*)(out + obase + 2 * SUBBAND_STRIDE) = hl;
    *(float2*)(out + obase + 3 * SUBBAND_STRIDE) = hh;
}

extern "C" void kernel_launch(void* const* d_in, const int* in_sizes, int n_in,
                              void* d_out, int out_size)
{
    const float* x = (const float*)d_in[0];
    float* out = (float*)d_out;

    // total threads = 512 planes * 256 rows * 128 pairs = 16,777,216
    const unsigned total = 512u * 256u * 128u;
    const unsigned grid = total / BLOCK; // 16384
    haar_dwt2_kernel<<<grid, BLOCK>>>(x, out);
}